// round 14
// baseline (speedup 1.0000x reference)
#include <cuda_runtime.h>
#include <math.h>
#include <stdint.h>

#define T_DIM 256
#define S_DIM 2048
#define C_DIM 128
#define G3    192
#define L_DIM 64

typedef unsigned long long ull;

// Scratch gx = h_proj @ W_ih^T + b_ih, layout [t][j][s]
__device__ float g_gx[(size_t)T_DIM * G3 * S_DIM];

// ---- packed f32x2 helpers ----
__device__ __forceinline__ ull dup2(float x) {
    ull r; asm("mov.b64 %0, {%1, %1};" : "=l"(r) : "f"(x)); return r;
}
__device__ __forceinline__ void fma2(ull& d, ull a, ull b) {
    asm("fma.rn.f32x2 %0, %1, %2, %0;" : "+l"(d) : "l"(a), "l"(b));
}
__device__ __forceinline__ float2 unpk(ull v) {
    float2 f; asm("mov.b64 {%0, %1}, %2;" : "=f"(f.x), "=f"(f.y) : "l"(v)); return f;
}

// ---- tf32 mma helpers (phase 1) ----
__device__ __forceinline__ uint32_t tf32b(float f) {
    uint32_t r; asm("cvt.rna.tf32.f32 %0, %1;" : "=r"(r) : "f"(f)); return r;
}
__device__ __forceinline__ float tf32f(float f) { return __uint_as_float(tf32b(f)); }

__device__ __forceinline__ void mma_tf32(float4& d,
    uint32_t a0, uint32_t a1, uint32_t a2, uint32_t a3,
    uint32_t b0, uint32_t b1)
{
    asm volatile(
      "mma.sync.aligned.m16n8k8.row.col.f32.tf32.tf32.f32 "
      "{%0,%1,%2,%3}, {%4,%5,%6,%7}, {%8,%9}, {%0,%1,%2,%3};"
      : "+f"(d.x), "+f"(d.y), "+f"(d.z), "+f"(d.w)
      : "r"(a0), "r"(a1), "r"(a2), "r"(a3), "r"(b0), "r"(b1));
}

// ---------------------------------------------------------------------------
// Phase 1 (tensor cores, smem-staged) — EXACT R7 version (~449us measured).
// ---------------------------------------------------------------------------
#define BS1_OFF   0
#define BS2_OFF   4096
#define BS3_OFF   6144
#define B1_OFF    18432
#define B2_OFF    18464
#define BIH_OFF   18528
#define H1_OFF    18720
#define X_OFF     23328
#define H2_OFF    23328
#define CHK_OFF   32032
#define SM1_TOT   40224

__global__ void __launch_bounds__(256) mlp_gx_tensor(
    const float* __restrict__ x,
    const float* __restrict__ W1, const float* __restrict__ b1,
    const float* __restrict__ W2, const float* __restrict__ b2,
    const float* __restrict__ Wih, const float* __restrict__ bih)
{
    extern __shared__ float sm[];
    const int tid  = threadIdx.x;
    const int w    = tid >> 5;
    const int lane = tid & 31;
    const int gid  = lane >> 2;
    const int tig  = lane & 3;

    for (int i = tid; i < 4096; i += 256) {
        int k = i >> 5, n = i & 31;
        sm[BS1_OFF + (n >> 3) * 1024 + k * 8 + (n & 7)] = tf32f(W1[i]);
    }
    for (int i = tid; i < 2048; i += 256) {
        int k = i >> 6, n = i & 63;
        sm[BS2_OFF + (n >> 3) * 256 + k * 8 + (n & 7)] = tf32f(W2[i]);
    }
    for (int i = tid; i < 12288; i += 256) {
        int n = i >> 6, k = i & 63;
        sm[BS3_OFF + (n >> 3) * 512 + k * 8 + (n & 7)] = tf32f(Wih[i]);
    }
    if (tid < 32)  sm[B1_OFF + tid]  = b1[tid];
    if (tid < 64)  sm[B2_OFF + tid]  = b2[tid];
    if (tid < 192) sm[BIH_OFF + tid] = bih[tid];

    const int rowblock = blockIdx.x * 128;
    const int t  = rowblock >> 11;
    const int s0 = (rowblock & 2047) + w * 16;

    {
        const float4* xg = reinterpret_cast<const float4*>(x) + (size_t)rowblock * 32;
        #pragma unroll
        for (int it = 0; it < 16; it++) {
            int fi = tid + it * 256;
            int r = fi >> 5, c4 = fi & 31;
            float4 v = __ldg(&xg[(size_t)r * 32 + c4]);
            *reinterpret_cast<float4*>(&sm[X_OFF + r * 132 + c4 * 4]) = v;
        }
    }
    __syncthreads();

    float* h1w = sm + H1_OFF + w * (16 * 36);
    const float* xw0 = sm + X_OFF + (w * 16 + 0) * 132;
    const float* xw8 = sm + X_OFF + (w * 16 + 8) * 132;

    float4 acc1[4];
    #pragma unroll
    for (int nt = 0; nt < 4; nt++) {
        float bx = sm[B1_OFF + nt * 8 + 2 * tig];
        float by = sm[B1_OFF + nt * 8 + 2 * tig + 1];
        acc1[nt] = make_float4(bx, by, bx, by);
    }
    #pragma unroll
    for (int k0 = 0; k0 < 16; k0++) {
        int k = k0 * 8;
        uint32_t a0 = tf32b(xw0[gid * 132 + k + tig]);
        uint32_t a1 = tf32b(xw8[gid * 132 + k + tig]);
        uint32_t a2 = tf32b(xw0[gid * 132 + k + tig + 4]);
        uint32_t a3 = tf32b(xw8[gid * 132 + k + tig + 4]);
        #pragma unroll
        for (int nt = 0; nt < 4; nt++) {
            uint32_t bb0 = __float_as_uint(sm[BS1_OFF + nt * 1024 + (k + tig) * 8 + gid]);
            uint32_t bb1 = __float_as_uint(sm[BS1_OFF + nt * 1024 + (k + tig + 4) * 8 + gid]);
            mma_tf32(acc1[nt], a0, a1, a2, a3, bb0, bb1);
        }
    }
    #pragma unroll
    for (int nt = 0; nt < 4; nt++) {
        int c = nt * 8 + 2 * tig;
        float vx = acc1[nt].x, vy = acc1[nt].y, vz = acc1[nt].z, vw = acc1[nt].w;
        h1w[gid * 36 + c]           = tf32f(fmaxf(vx, 0.01f * vx));
        h1w[gid * 36 + c + 1]       = tf32f(fmaxf(vy, 0.01f * vy));
        h1w[(gid + 8) * 36 + c]     = tf32f(fmaxf(vz, 0.01f * vz));
        h1w[(gid + 8) * 36 + c + 1] = tf32f(fmaxf(vw, 0.01f * vw));
    }
    __syncthreads();

    float* h2w = sm + H2_OFF + w * (16 * 68);
    float* chk = sm + CHK_OFF + w * (32 * 20);

    uint32_t areg2[16];
    #pragma unroll
    for (int k0 = 0; k0 < 4; k0++) {
        int k = k0 * 8;
        areg2[k0*4+0] = __float_as_uint(h1w[gid * 36 + k + tig]);
        areg2[k0*4+1] = __float_as_uint(h1w[(gid + 8) * 36 + k + tig]);
        areg2[k0*4+2] = __float_as_uint(h1w[gid * 36 + k + tig + 4]);
        areg2[k0*4+3] = __float_as_uint(h1w[(gid + 8) * 36 + k + tig + 4]);
    }
    float4 acc2[8];
    #pragma unroll
    for (int nt = 0; nt < 8; nt++) {
        float bx = sm[B2_OFF + nt * 8 + 2 * tig];
        float by = sm[B2_OFF + nt * 8 + 2 * tig + 1];
        acc2[nt] = make_float4(bx, by, bx, by);
    }
    #pragma unroll
    for (int k0 = 0; k0 < 4; k0++) {
        int k = k0 * 8;
        #pragma unroll
        for (int nt = 0; nt < 8; nt++) {
            uint32_t bb0 = __float_as_uint(sm[BS2_OFF + nt * 256 + (k + tig) * 8 + gid]);
            uint32_t bb1 = __float_as_uint(sm[BS2_OFF + nt * 256 + (k + tig + 4) * 8 + gid]);
            mma_tf32(acc2[nt], areg2[k0*4+0], areg2[k0*4+1], areg2[k0*4+2], areg2[k0*4+3], bb0, bb1);
        }
    }
    #pragma unroll
    for (int nt = 0; nt < 8; nt++) {
        int c = nt * 8 + 2 * tig;
        float vx = acc2[nt].x, vy = acc2[nt].y, vz = acc2[nt].z, vw = acc2[nt].w;
        h2w[gid * 68 + c]           = tf32f(fmaxf(vx, 0.01f * vx));
        h2w[gid * 68 + c + 1]       = tf32f(fmaxf(vy, 0.01f * vy));
        h2w[(gid + 8) * 68 + c]     = tf32f(fmaxf(vz, 0.01f * vz));
        h2w[(gid + 8) * 68 + c + 1] = tf32f(fmaxf(vw, 0.01f * vw));
    }
    __syncwarp();

    uint32_t areg3[32];
    #pragma unroll
    for (int k0 = 0; k0 < 8; k0++) {
        int k = k0 * 8;
        areg3[k0*4+0] = __float_as_uint(h2w[gid * 68 + k + tig]);
        areg3[k0*4+1] = __float_as_uint(h2w[(gid + 8) * 68 + k + tig]);
        areg3[k0*4+2] = __float_as_uint(h2w[gid * 68 + k + tig + 4]);
        areg3[k0*4+3] = __float_as_uint(h2w[(gid + 8) * 68 + k + tig + 4]);
    }

    float* gx_t = g_gx + (size_t)t * G3 * S_DIM + s0;
    #pragma unroll 1
    for (int ch = 0; ch < 6; ch++) {
        float4 acc3[4];
        #pragma unroll
        for (int nt = 0; nt < 4; nt++) {
            float bx = sm[BIH_OFF + ch * 32 + nt * 8 + 2 * tig];
            float by = sm[BIH_OFF + ch * 32 + nt * 8 + 2 * tig + 1];
            acc3[nt] = make_float4(bx, by, bx, by);
        }
        #pragma unroll
        for (int k0 = 0; k0 < 8; k0++) {
            int k = k0 * 8;
            #pragma unroll
            for (int nt = 0; nt < 4; nt++) {
                int nb = (ch * 4 + nt) * 512;
                uint32_t bb0 = __float_as_uint(sm[BS3_OFF + nb + (k + tig) * 8 + gid]);
                uint32_t bb1 = __float_as_uint(sm[BS3_OFF + nb + (k + tig + 4) * 8 + gid]);
                mma_tf32(acc3[nt], areg3[k0*4+0], areg3[k0*4+1], areg3[k0*4+2], areg3[k0*4+3], bb0, bb1);
            }
        }
        #pragma unroll
        for (int nt = 0; nt < 4; nt++) {
            int c = nt * 8 + 2 * tig;
            chk[c * 20 + gid]           = acc3[nt].x;
            chk[(c + 1) * 20 + gid]     = acc3[nt].y;
            chk[c * 20 + gid + 8]       = acc3[nt].z;
            chk[(c + 1) * 20 + gid + 8] = acc3[nt].w;
        }
        __syncwarp();
        #pragma unroll
        for (int q8 = 0; q8 < 4; q8++) {
            int j = q8 * 8 + gid;
            float4 v = *reinterpret_cast<const float4*>(&chk[j * 20 + tig * 4]);
            *reinterpret_cast<float4*>(gx_t + (size_t)(ch * 32 + j) * S_DIM + tig * 4) = v;
        }
        __syncwarp();
    }
}

// ---------------------------------------------------------------------------
// Phase 2: GRU. 256 blocks x 256 threads, 8 stocks/block, 2 blocks/SM.
// Thread = (j 0..63, kq 0..3 k-quarter): owns all 3 gates of column j over
// 16 k's. Per k: 2 broadcast LDS.128 (quarters pad-staggered, conflict-free)
// feed 12 fma2 on 12 independent chains. kq partials reduced via 2-stage
// shfl_xor butterfly; kq==0 lane stores gh to smem; gate math 2 stocks/thread.
// ---------------------------------------------------------------------------
#define HQ(k) ((k) * 8 + ((k) >> 4) * 4)   // h_s index with +4 pad per 16-k quarter

__global__ void __launch_bounds__(256, 2) gru_kernel(
    const float* __restrict__ Whh, const float* __restrict__ bhh,
    float* __restrict__ out)
{
    __shared__ float h_s[64 * 8 + 12];   // [k][s], +4 pad per quarter
    __shared__ float gx_s[192 * 8];      // [j][s]
    __shared__ float gh_s[192 * 8];      // [g*64+j][s]

    const int tid = threadIdx.x;
    const int kq  = tid & 3;             // k quarter: [kq*16, kq*16+16)
    const int j   = tid >> 2;            // hidden column 0..63
    const int s0  = blockIdx.x * 8;

    // Weights for 3 gates of column j, this k-quarter (16 each = 48 regs)
    float wR[16], wZ[16], wN[16];
    {
        const float4* pR = reinterpret_cast<const float4*>(Whh + (size_t)(      j) * L_DIM + kq * 16);
        const float4* pZ = reinterpret_cast<const float4*>(Whh + (size_t)( 64 + j) * L_DIM + kq * 16);
        const float4* pN = reinterpret_cast<const float4*>(Whh + (size_t)(128 + j) * L_DIM + kq * 16);
        #pragma unroll
        for (int q = 0; q < 4; q++) {
            float4 vR = __ldg(&pR[q]);
            float4 vZ = __ldg(&pZ[q]);
            float4 vN = __ldg(&pN[q]);
            wR[q*4+0]=vR.x; wR[q*4+1]=vR.y; wR[q*4+2]=vR.z; wR[q*4+3]=vR.w;
            wZ[q*4+0]=vZ.x; wZ[q*4+1]=vZ.y; wZ[q*4+2]=vZ.z; wZ[q*4+3]=vZ.w;
            wN[q*4+0]=vN.x; wN[q*4+1]=vN.y; wN[q*4+2]=vN.z; wN[q*4+3]=vN.w;
        }
    }
    const ull bR = (kq == 0) ? dup2(__ldg(&bhh[      j])) : 0ULL;
    const ull bZ = (kq == 0) ? dup2(__ldg(&bhh[ 64 + j])) : 0ULL;
    const ull bN = (kq == 0) ? dup2(__ldg(&bhh[128 + j])) : 0ULL;

    for (int i = tid; i < 64 * 8 + 12; i += 256) h_s[i] = 0.0f;
    __syncthreads();

    const float* hp = h_s + kq * 132;    // 16*8 + 4 pad per quarter

    for (int t = 0; t < T_DIM; t++) {
        // Prefetch this step's gx tile (1536 floats, 6/thread)
        float gbuf[6];
        #pragma unroll
        for (int i = 0; i < 6; i++) {
            int idx = tid + 256 * i;
            int jj = idx >> 3, ss = idx & 7;
            gbuf[i] = __ldg(&g_gx[((size_t)t * G3 + jj) * S_DIM + s0 + ss]);
        }

        // Partial gh for 3 gates x 8 stocks over this quarter's 16 k's
        ull aR0 = bR, aR1 = bR, aR2 = bR, aR3 = bR;
        ull aZ0 = bZ, aZ1 = bZ, aZ2 = bZ, aZ3 = bZ;
        ull aN0 = bN, aN1 = bN, aN2 = bN, aN3 = bN;
        #pragma unroll
        for (int k = 0; k < 16; k++) {
            ulonglong2 hA = *reinterpret_cast<const ulonglong2*>(hp + k * 8);
            ulonglong2 hB = *reinterpret_cast<const ulonglong2*>(hp + k * 8 + 4);
            ull dR = dup2(wR[k]);
            fma2(aR0, hA.x, dR); fma2(aR1, hA.y, dR);
            fma2(aR2, hB.x, dR); fma2(aR3, hB.y, dR);
            ull dZ = dup2(wZ[k]);
            fma2(aZ0, hA.x, dZ); fma2(aZ1, hA.y, dZ);
            fma2(aZ2, hB.x, dZ); fma2(aZ3, hB.y, dZ);
            ull dN = dup2(wN[k]);
            fma2(aN0, hA.x, dN); fma2(aN1, hA.y, dN);
            fma2(aN2, hB.x, dN); fma2(aN3, hB.y, dN);
        }

        // Butterfly-reduce over kq (lane bits 0-1); kq==0 stores to gh_s
        {
            float2 r0 = unpk(aR0), r1 = unpk(aR1), r2 = unpk(aR2), r3 = unpk(aR3);
            float2 z0 = unpk(aZ0), z1 = unpk(aZ1), z2 = unpk(aZ2), z3 = unpk(aZ3);
            float2 n0 = unpk(aN0), n1 = unpk(aN1), n2 = unpk(aN2), n3 = unpk(aN3);
            float g[24] = {r0.x,r0.y,r1.x,r1.y,r2.x,r2.y,r3.x,r3.y,
                           z0.x,z0.y,z1.x,z1.y,z2.x,z2.y,z3.x,z3.y,
                           n0.x,n0.y,n1.x,n1.y,n2.x,n2.y,n3.x,n3.y};
            #pragma unroll
            for (int i = 0; i < 24; i++) {
                g[i] += __shfl_xor_sync(0xFFFFFFFFu, g[i], 1);
                g[i] += __shfl_xor_sync(0xFFFFFFFFu, g[i], 2);
            }
            if (kq == 0) {
                *reinterpret_cast<float4*>(&gh_s[(      j) * 8    ]) = make_float4(g[0],  g[1],  g[2],  g[3]);
                *reinterpret_cast<float4*>(&gh_s[(      j) * 8 + 4]) = make_float4(g[4],  g[5],  g[6],  g[7]);
                *reinterpret_cast<float4*>(&gh_s[( 64 + j) * 8    ]) = make_float4(g[8],  g[9],  g[10], g[11]);
                *reinterpret_cast<float4*>(&gh_s[( 64 + j) * 8 + 4]) = make_float4(g[12], g[13], g[14], g[15]);
                *reinterpret_cast<float4*>(&gh_s[(128 + j) * 8    ]) = make_float4(g[16], g[17], g[18], g[19]);
                *reinterpret_cast<float4*>(&gh_s[(128 + j) * 8 + 4]) = make_float4(g[20], g[21], g[22], g[23]);
            }
        }

        // Stage gx into shared [j][s]
        #pragma unroll
        for (int i = 0; i < 6; i++) {
            int idx = tid + 256 * i;
            int jj = idx >> 3, ss = idx & 7;
            gx_s[jj * 8 + ss] = gbuf[i];
        }
        __syncthreads();   // gh + gx visible; all GEMM reads of old h done

        // Gate math: column j, stocks 2kq, 2kq+1
        {
            const int sb = 2 * kq;
            float2 ghr = *reinterpret_cast<const float2*>(&gh_s[(      j) * 8 + sb]);
            float2 ghz = *reinterpret_cast<const float2*>(&gh_s[( 64 + j) * 8 + sb]);
            float2 ghn = *reinterpret_cast<const float2*>(&gh_s[(128 + j) * 8 + sb]);
            float2 gxr = *reinterpret_cast<const float2*>(&gx_s[(      j) * 8 + sb]);
            float2 gxz = *reinterpret_cast<const float2*>(&gx_s[( 64 + j) * 8 + sb]);
            float2 gxn = *reinterpret_cast<const float2*>(&gx_s[(128 + j) * 8 + sb]);
            float2 ho  = *reinterpret_cast<const float2*>(&h_s[HQ(j) + sb - ((j & 15) * 0)]);
            // NOTE: h column j lives at HQ(j)=j*8+(j>>4)*4; sb offset within row
            ho = *reinterpret_cast<const float2*>(&h_s[j * 8 + (j >> 4) * 4 + sb]);

            float hn[2];
            #pragma unroll
            for (int e = 0; e < 2; e++) {
                float ghrv = e ? ghr.y : ghr.x, ghzv = e ? ghz.y : ghz.x, ghnv = e ? ghn.y : ghn.x;
                float gxrv = e ? gxr.y : gxr.x, gxzv = e ? gxz.y : gxz.x, gxnv = e ? gxn.y : gxn.x;
                float hov = e ? ho.y : ho.x;
                float rr = 1.0f / (1.0f + __expf(-(gxrv + ghrv)));
                float zz = 1.0f / (1.0f + __expf(-(gxzv + ghzv)));
                float narg = gxnv + rr * ghnv;
                float ex = __expf(-2.0f * fabsf(narg));
                float nn = (1.0f - ex) / (1.0f + ex);
                nn = copysignf(nn, narg);
                hn[e] = (1.0f - zz) * nn + zz * hov;
            }
            *reinterpret_cast<ull*>(&h_s[j * 8 + (j >> 4) * 4 + sb]) =
                *reinterpret_cast<const ull*>(hn);
        }
        __syncthreads();   // new h visible before next step's GEMM
    }

    // Final hidden state: out[(s0+s)*64 + j]
    for (int idx = tid; idx < 512; idx += 256) {
        int jj = idx & 63, ss = idx >> 6;
        out[(size_t)(s0 + ss) * L_DIM + jj] = h_s[jj * 8 + (jj >> 4) * 4 + ss];
    }
}

// ---------------------------------------------------------------------------
extern "C" void kernel_launch(void* const* d_in, const int* in_sizes, int n_in,
                              void* d_out, int out_size)
{
    const float* x   = (const float*)d_in[0];
    const float* W1  = (const float*)d_in[1];
    const float* b1  = (const float*)d_in[2];
    const float* W2  = (const float*)d_in[3];
    const float* b2  = (const float*)d_in[4];
    const float* Wih = (const float*)d_in[5];
    const float* Whh = (const float*)d_in[6];
    const float* bih = (const float*)d_in[7];
    const float* bhh = (const float*)d_in[8];
    float* out = (float*)d_out;

    static bool attrs_set = false;
    if (!attrs_set) {
        cudaFuncSetAttribute(mlp_gx_tensor,
                             cudaFuncAttributeMaxDynamicSharedMemorySize, SM1_TOT * 4);
        attrs_set = true;
    }

    // Phase 1: 4096 blocks x 256 threads; 128 rows per block (smem-staged)
    mlp_gx_tensor<<<4096, 256, SM1_TOT * 4>>>(x, W1, b1, W2, b2, Wih, bih);
    // Phase 2: GRU, 256 blocks x 256 threads, 8 stocks/block, 2 blocks/SM
    gru_kernel<<<256, 256>>>(Whh, bhh, out);
}

// round 15
// speedup vs baseline: 1.0183x; 1.0183x over previous
#include <cuda_runtime.h>
#include <math.h>
#include <stdint.h>

#define T_DIM 256
#define S_DIM 2048
#define C_DIM 128
#define G3    192
#define L_DIM 64

typedef unsigned long long ull;

// Scratch gx = h_proj @ W_ih^T + b_ih, layout [t][j][s]
__device__ float g_gx[(size_t)T_DIM * G3 * S_DIM];

// ---- packed f32x2 helpers ----
__device__ __forceinline__ ull dup2(float x) {
    ull r; asm("mov.b64 %0, {%1, %1};" : "=l"(r) : "f"(x)); return r;
}
__device__ __forceinline__ void fma2(ull& d, ull a, ull b) {
    asm("fma.rn.f32x2 %0, %1, %2, %0;" : "+l"(d) : "l"(a), "l"(b));
}
__device__ __forceinline__ float2 unpk(ull v) {
    float2 f; asm("mov.b64 {%0, %1}, %2;" : "=f"(f.x), "=f"(f.y) : "l"(v)); return f;
}

// ---- tf32 mma helpers (phase 1) ----
__device__ __forceinline__ uint32_t tf32b(float f) {
    uint32_t r; asm("cvt.rna.tf32.f32 %0, %1;" : "=r"(r) : "f"(f)); return r;
}
__device__ __forceinline__ float tf32f(float f) { return __uint_as_float(tf32b(f)); }

__device__ __forceinline__ void mma_tf32(float4& d,
    uint32_t a0, uint32_t a1, uint32_t a2, uint32_t a3,
    uint32_t b0, uint32_t b1)
{
    asm volatile(
      "mma.sync.aligned.m16n8k8.row.col.f32.tf32.tf32.f32 "
      "{%0,%1,%2,%3}, {%4,%5,%6,%7}, {%8,%9}, {%0,%1,%2,%3};"
      : "+f"(d.x), "+f"(d.y), "+f"(d.z), "+f"(d.w)
      : "r"(a0), "r"(a1), "r"(a2), "r"(a3), "r"(b0), "r"(b1));
}

// ---------------------------------------------------------------------------
// Phase 1 (tensor cores, smem-staged). Deep-pipelined version:
//   GEMM1: k split even/odd into 2 acc sets -> 8 independent mma chains.
//   GEMM3: single pass over all 192 columns with 24 float4 accumulators
//          (24 independent chains) instead of 6 serial 4-chain chunks.
// Everything else identical to the measured R7 kernel.
// ---------------------------------------------------------------------------
#define BS1_OFF   0
#define BS2_OFF   4096
#define BS3_OFF   6144
#define B1_OFF    18432
#define B2_OFF    18464
#define BIH_OFF   18528
#define H1_OFF    18720
#define X_OFF     23328
#define H2_OFF    23328
#define CHK_OFF   32032
#define SM1_TOT   40224

__global__ void __launch_bounds__(256) mlp_gx_tensor(
    const float* __restrict__ x,
    const float* __restrict__ W1, const float* __restrict__ b1,
    const float* __restrict__ W2, const float* __restrict__ b2,
    const float* __restrict__ Wih, const float* __restrict__ bih)
{
    extern __shared__ float sm[];
    const int tid  = threadIdx.x;
    const int w    = tid >> 5;
    const int lane = tid & 31;
    const int gid  = lane >> 2;
    const int tig  = lane & 3;

    for (int i = tid; i < 4096; i += 256) {
        int k = i >> 5, n = i & 31;
        sm[BS1_OFF + (n >> 3) * 1024 + k * 8 + (n & 7)] = tf32f(W1[i]);
    }
    for (int i = tid; i < 2048; i += 256) {
        int k = i >> 6, n = i & 63;
        sm[BS2_OFF + (n >> 3) * 256 + k * 8 + (n & 7)] = tf32f(W2[i]);
    }
    for (int i = tid; i < 12288; i += 256) {
        int n = i >> 6, k = i & 63;
        sm[BS3_OFF + (n >> 3) * 512 + k * 8 + (n & 7)] = tf32f(Wih[i]);
    }
    if (tid < 32)  sm[B1_OFF + tid]  = b1[tid];
    if (tid < 64)  sm[B2_OFF + tid]  = b2[tid];
    if (tid < 192) sm[BIH_OFF + tid] = bih[tid];

    const int rowblock = blockIdx.x * 128;
    const int t  = rowblock >> 11;
    const int s0 = (rowblock & 2047) + w * 16;

    {
        const float4* xg = reinterpret_cast<const float4*>(x) + (size_t)rowblock * 32;
        #pragma unroll
        for (int it = 0; it < 16; it++) {
            int fi = tid + it * 256;
            int r = fi >> 5, c4 = fi & 31;
            float4 v = __ldg(&xg[(size_t)r * 32 + c4]);
            *reinterpret_cast<float4*>(&sm[X_OFF + r * 132 + c4 * 4]) = v;
        }
    }
    __syncthreads();

    float* h1w = sm + H1_OFF + w * (16 * 36);
    const float* xw0 = sm + X_OFF + (w * 16 + 0) * 132;
    const float* xw8 = sm + X_OFF + (w * 16 + 8) * 132;

    // ========== GEMM1: x(16x128) @ W1(128x32), 8 independent chains ==========
    float4 acc1[4], acc1b[4];
    #pragma unroll
    for (int nt = 0; nt < 4; nt++) {
        float bx = sm[B1_OFF + nt * 8 + 2 * tig];
        float by = sm[B1_OFF + nt * 8 + 2 * tig + 1];
        acc1[nt]  = make_float4(bx, by, bx, by);
        acc1b[nt] = make_float4(0.f, 0.f, 0.f, 0.f);
    }
    #pragma unroll
    for (int k0 = 0; k0 < 16; k0++) {
        int k = k0 * 8;
        uint32_t a0 = tf32b(xw0[gid * 132 + k + tig]);
        uint32_t a1 = tf32b(xw8[gid * 132 + k + tig]);
        uint32_t a2 = tf32b(xw0[gid * 132 + k + tig + 4]);
        uint32_t a3 = tf32b(xw8[gid * 132 + k + tig + 4]);
        float4* accs = (k0 & 1) ? acc1b : acc1;
        #pragma unroll
        for (int nt = 0; nt < 4; nt++) {
            uint32_t bb0 = __float_as_uint(sm[BS1_OFF + nt * 1024 + (k + tig) * 8 + gid]);
            uint32_t bb1 = __float_as_uint(sm[BS1_OFF + nt * 1024 + (k + tig + 4) * 8 + gid]);
            mma_tf32(accs[nt], a0, a1, a2, a3, bb0, bb1);
        }
    }
    #pragma unroll
    for (int nt = 0; nt < 4; nt++) {
        acc1[nt].x += acc1b[nt].x; acc1[nt].y += acc1b[nt].y;
        acc1[nt].z += acc1b[nt].z; acc1[nt].w += acc1b[nt].w;
    }
    #pragma unroll
    for (int nt = 0; nt < 4; nt++) {
        int c = nt * 8 + 2 * tig;
        float vx = acc1[nt].x, vy = acc1[nt].y, vz = acc1[nt].z, vw = acc1[nt].w;
        h1w[gid * 36 + c]           = tf32f(fmaxf(vx, 0.01f * vx));
        h1w[gid * 36 + c + 1]       = tf32f(fmaxf(vy, 0.01f * vy));
        h1w[(gid + 8) * 36 + c]     = tf32f(fmaxf(vz, 0.01f * vz));
        h1w[(gid + 8) * 36 + c + 1] = tf32f(fmaxf(vw, 0.01f * vw));
    }
    __syncthreads();

    float* h2w = sm + H2_OFF + w * (16 * 68);
    float* chk = sm + CHK_OFF + w * (32 * 20);

    // ========== GEMM2: h1(16x32) @ W2(32x64), 8 chains (unchanged) ==========
    uint32_t areg2[16];
    #pragma unroll
    for (int k0 = 0; k0 < 4; k0++) {
        int k = k0 * 8;
        areg2[k0*4+0] = __float_as_uint(h1w[gid * 36 + k + tig]);
        areg2[k0*4+1] = __float_as_uint(h1w[(gid + 8) * 36 + k + tig]);
        areg2[k0*4+2] = __float_as_uint(h1w[gid * 36 + k + tig + 4]);
        areg2[k0*4+3] = __float_as_uint(h1w[(gid + 8) * 36 + k + tig + 4]);
    }
    float4 acc2[8];
    #pragma unroll
    for (int nt = 0; nt < 8; nt++) {
        float bx = sm[B2_OFF + nt * 8 + 2 * tig];
        float by = sm[B2_OFF + nt * 8 + 2 * tig + 1];
        acc2[nt] = make_float4(bx, by, bx, by);
    }
    #pragma unroll
    for (int k0 = 0; k0 < 4; k0++) {
        int k = k0 * 8;
        #pragma unroll
        for (int nt = 0; nt < 8; nt++) {
            uint32_t bb0 = __float_as_uint(sm[BS2_OFF + nt * 256 + (k + tig) * 8 + gid]);
            uint32_t bb1 = __float_as_uint(sm[BS2_OFF + nt * 256 + (k + tig + 4) * 8 + gid]);
            mma_tf32(acc2[nt], areg2[k0*4+0], areg2[k0*4+1], areg2[k0*4+2], areg2[k0*4+3], bb0, bb1);
        }
    }
    #pragma unroll
    for (int nt = 0; nt < 8; nt++) {
        int c = nt * 8 + 2 * tig;
        float vx = acc2[nt].x, vy = acc2[nt].y, vz = acc2[nt].z, vw = acc2[nt].w;
        h2w[gid * 68 + c]           = tf32f(fmaxf(vx, 0.01f * vx));
        h2w[gid * 68 + c + 1]       = tf32f(fmaxf(vy, 0.01f * vy));
        h2w[(gid + 8) * 68 + c]     = tf32f(fmaxf(vz, 0.01f * vz));
        h2w[(gid + 8) * 68 + c + 1] = tf32f(fmaxf(vw, 0.01f * vw));
    }
    __syncwarp();

    // ====== GEMM3: h2(16x64) @ Wih^T(64x192), ONE pass, 24 acc chains ======
    uint32_t areg3[32];
    #pragma unroll
    for (int k0 = 0; k0 < 8; k0++) {
        int k = k0 * 8;
        areg3[k0*4+0] = __float_as_uint(h2w[gid * 68 + k + tig]);
        areg3[k0*4+1] = __float_as_uint(h2w[(gid + 8) * 68 + k + tig]);
        areg3[k0*4+2] = __float_as_uint(h2w[gid * 68 + k + tig + 4]);
        areg3[k0*4+3] = __float_as_uint(h2w[(gid + 8) * 68 + k + tig + 4]);
    }

    float4 acc3[24];
    #pragma unroll
    for (int nt = 0; nt < 24; nt++) {
        float bx = sm[BIH_OFF + nt * 8 + 2 * tig];
        float by = sm[BIH_OFF + nt * 8 + 2 * tig + 1];
        acc3[nt] = make_float4(bx, by, bx, by);
    }
    #pragma unroll
    for (int k0 = 0; k0 < 8; k0++) {
        int k = k0 * 8;
        #pragma unroll
        for (int nt = 0; nt < 24; nt++) {
            uint32_t bb0 = __float_as_uint(sm[BS3_OFF + nt * 512 + (k + tig) * 8 + gid]);
            uint32_t bb1 = __float_as_uint(sm[BS3_OFF + nt * 512 + (k + tig + 4) * 8 + gid]);
            mma_tf32(acc3[nt], areg3[k0*4+0], areg3[k0*4+1], areg3[k0*4+2], areg3[k0*4+3], bb0, bb1);
        }
    }

    // Transpose + store, 4 N-tiles (32 columns) at a time through chk
    float* gx_t = g_gx + (size_t)t * G3 * S_DIM + s0;
    #pragma unroll
    for (int ch = 0; ch < 6; ch++) {
        #pragma unroll
        for (int q = 0; q < 4; q++) {
            int nt = ch * 4 + q;
            int c = q * 8 + 2 * tig;
            chk[c * 20 + gid]           = acc3[nt].x;
            chk[(c + 1) * 20 + gid]     = acc3[nt].y;
            chk[c * 20 + gid + 8]       = acc3[nt].z;
            chk[(c + 1) * 20 + gid + 8] = acc3[nt].w;
        }
        __syncwarp();
        #pragma unroll
        for (int q8 = 0; q8 < 4; q8++) {
            int j = q8 * 8 + gid;
            float4 v = *reinterpret_cast<const float4*>(&chk[j * 20 + tig * 4]);
            *reinterpret_cast<float4*>(gx_t + (size_t)(ch * 32 + j) * S_DIM + tig * 4) = v;
        }
        __syncwarp();
    }
}

// ---------------------------------------------------------------------------
// Phase 2: GRU — EXACT R13 version (best measured, 577us).
// 256 blocks x 128 threads, 8 stocks/block. Thread = (j 0..63, kq 0..1):
// all 3 gates of column j; 12 independent fma2 chains per k-pair of LDS.
// ---------------------------------------------------------------------------
__global__ void __launch_bounds__(128, 2) gru_kernel(
    const float* __restrict__ Whh, const float* __restrict__ bhh,
    float* __restrict__ out)
{
    __shared__ float h_s[64 * 8];      // [k][s]
    __shared__ float gx_s[192 * 8];    // [j][s]

    const int tid = threadIdx.x;
    const int kq  = tid & 1;           // k half: [kq*32, kq*32+32)
    const int j   = tid >> 1;          // hidden column 0..63
    const int s0  = blockIdx.x * 8;

    float wR[32], wZ[32], wN[32];
    {
        const float4* pR = reinterpret_cast<const float4*>(Whh + (size_t)(      j) * L_DIM + kq * 32);
        const float4* pZ = reinterpret_cast<const float4*>(Whh + (size_t)( 64 + j) * L_DIM + kq * 32);
        const float4* pN = reinterpret_cast<const float4*>(Whh + (size_t)(128 + j) * L_DIM + kq * 32);
        #pragma unroll
        for (int q = 0; q < 8; q++) {
            float4 vR = __ldg(&pR[q]);
            float4 vZ = __ldg(&pZ[q]);
            float4 vN = __ldg(&pN[q]);
            wR[q*4+0]=vR.x; wR[q*4+1]=vR.y; wR[q*4+2]=vR.z; wR[q*4+3]=vR.w;
            wZ[q*4+0]=vZ.x; wZ[q*4+1]=vZ.y; wZ[q*4+2]=vZ.z; wZ[q*4+3]=vZ.w;
            wN[q*4+0]=vN.x; wN[q*4+1]=vN.y; wN[q*4+2]=vN.z; wN[q*4+3]=vN.w;
        }
    }
    const ull bR = (kq == 0) ? dup2(__ldg(&bhh[      j])) : 0ULL;
    const ull bZ = (kq == 0) ? dup2(__ldg(&bhh[ 64 + j])) : 0ULL;
    const ull bN = (kq == 0) ? dup2(__ldg(&bhh[128 + j])) : 0ULL;

    for (int i = tid; i < 64 * 8; i += 128) h_s[i] = 0.0f;
    __syncthreads();

    const float* hp = h_s + kq * 32 * 8;

    for (int t = 0; t < T_DIM; t++) {
        float gbuf[12];
        #pragma unroll
        for (int i = 0; i < 12; i++) {
            int idx = tid + 128 * i;
            int jj = idx >> 3, ss = idx & 7;
            gbuf[i] = __ldg(&g_gx[((size_t)t * G3 + jj) * S_DIM + s0 + ss]);
        }

        ull aR0 = bR, aR1 = bR, aR2 = bR, aR3 = bR;
        ull aZ0 = bZ, aZ1 = bZ, aZ2 = bZ, aZ3 = bZ;
        ull aN0 = bN, aN1 = bN, aN2 = bN, aN3 = bN;
        #pragma unroll
        for (int k = 0; k < 32; k++) {
            ulonglong2 hA = *reinterpret_cast<const ulonglong2*>(hp + k * 8);
            ulonglong2 hB = *reinterpret_cast<const ulonglong2*>(hp + k * 8 + 4);
            ull dR = dup2(wR[k]);
            fma2(aR0, hA.x, dR); fma2(aR1, hA.y, dR);
            fma2(aR2, hB.x, dR); fma2(aR3, hB.y, dR);
            ull dZ = dup2(wZ[k]);
            fma2(aZ0, hA.x, dZ); fma2(aZ1, hA.y, dZ);
            fma2(aZ2, hB.x, dZ); fma2(aZ3, hB.y, dZ);
            ull dN = dup2(wN[k]);
            fma2(aN0, hA.x, dN); fma2(aN1, hA.y, dN);
            fma2(aN2, hB.x, dN); fma2(aN3, hB.y, dN);
        }

        float ghR[4], ghZ[4], ghN[4];
        {
            float2 r0 = unpk(aR0), r1 = unpk(aR1), r2 = unpk(aR2), r3 = unpk(aR3);
            float2 z0 = unpk(aZ0), z1 = unpk(aZ1), z2 = unpk(aZ2), z3 = unpk(aZ3);
            float2 n0 = unpk(aN0), n1 = unpk(aN1), n2 = unpk(aN2), n3 = unpk(aN3);
            float gr[8] = {r0.x,r0.y,r1.x,r1.y,r2.x,r2.y,r3.x,r3.y};
            float gz[8] = {z0.x,z0.y,z1.x,z1.y,z2.x,z2.y,z3.x,z3.y};
            float gn[8] = {n0.x,n0.y,n1.x,n1.y,n2.x,n2.y,n3.x,n3.y};
            #pragma unroll
            for (int i = 0; i < 8; i++) {
                gr[i] += __shfl_xor_sync(0xFFFFFFFFu, gr[i], 1);
                gz[i] += __shfl_xor_sync(0xFFFFFFFFu, gz[i], 1);
                gn[i] += __shfl_xor_sync(0xFFFFFFFFu, gn[i], 1);
            }
            #pragma unroll
            for (int e = 0; e < 4; e++) {
                ghR[e] = kq ? gr[4 + e] : gr[e];
                ghZ[e] = kq ? gz[4 + e] : gz[e];
                ghN[e] = kq ? gn[4 + e] : gn[e];
            }
        }

        #pragma unroll
        for (int i = 0; i < 12; i++) {
            int idx = tid + 128 * i;
            int jj = idx >> 3, ss = idx & 7;
            gx_s[jj * 8 + ss] = gbuf[i];
        }
        __syncthreads();

        {
            const int sb = kq * 4;
            float4 gxr = *reinterpret_cast<const float4*>(&gx_s[(      j) * 8 + sb]);
            float4 gxz = *reinterpret_cast<const float4*>(&gx_s[( 64 + j) * 8 + sb]);
            float4 gxn = *reinterpret_cast<const float4*>(&gx_s[(128 + j) * 8 + sb]);
            float4 hold = *reinterpret_cast<const float4*>(&h_s[j * 8 + sb]);
            float gxra[4] = {gxr.x, gxr.y, gxr.z, gxr.w};
            float gxza[4] = {gxz.x, gxz.y, gxz.z, gxz.w};
            float gxna[4] = {gxn.x, gxn.y, gxn.z, gxn.w};
            float hoa[4]  = {hold.x, hold.y, hold.z, hold.w};

            float hn[4];
            #pragma unroll
            for (int e = 0; e < 4; e++) {
                float rr = 1.0f / (1.0f + __expf(-(gxra[e] + ghR[e])));
                float zz = 1.0f / (1.0f + __expf(-(gxza[e] + ghZ[e])));
                float narg = gxna[e] + rr * ghN[e];
                float ex = __expf(-2.0f * fabsf(narg));
                float nn = (1.0f - ex) / (1.0f + ex);
                nn = copysignf(nn, narg);
                hn[e] = (1.0f - zz) * nn + zz * hoa[e];
            }
            *reinterpret_cast<float4*>(&h_s[j * 8 + sb]) =
                make_float4(hn[0], hn[1], hn[2], hn[3]);
        }
        __syncthreads();
    }

    for (int idx = tid; idx < 512; idx += 128) {
        int jj = idx & 63, ss = idx >> 6;
        out[(size_t)(s0 + ss) * L_DIM + jj] = h_s[jj * 8 + ss];
    }
}

// ---------------------------------------------------------------------------
extern "C" void kernel_launch(void* const* d_in, const int* in_sizes, int n_in,
                              void* d_out, int out_size)
{
    const float* x   = (const float*)d_in[0];
    const float* W1  = (const float*)d_in[1];
    const float* b1  = (const float*)d_in[2];
    const float* W2  = (const float*)d_in[3];
    const float* b2  = (const float*)d_in[4];
    const float* Wih = (const float*)d_in[5];
    const float* Whh = (const float*)d_in[6];
    const float* bih = (const float*)d_in[7];
    const float* bhh = (const float*)d_in[8];
    float* out = (float*)d_out;

    static bool attrs_set = false;
    if (!attrs_set) {
        cudaFuncSetAttribute(mlp_gx_tensor,
                             cudaFuncAttributeMaxDynamicSharedMemorySize, SM1_TOT * 4);
        attrs_set = true;
    }

    // Phase 1: 4096 blocks x 256 threads; 128 rows per block (smem-staged)
    mlp_gx_tensor<<<4096, 256, SM1_TOT * 4>>>(x, W1, b1, W2, b2, Wih, bih);
    // Phase 2: GRU, 256 blocks x 128 threads, 8 stocks/block
    gru_kernel<<<256, 128>>>(Whh, bhh, out);
}

// round 16
// speedup vs baseline: 1.2795x; 1.2565x over previous
#include <cuda_runtime.h>
#include <cuda_fp16.h>
#include <math.h>
#include <stdint.h>

#define T_DIM 256
#define S_DIM 2048
#define C_DIM 128
#define G3    192
#define L_DIM 64

typedef unsigned long long ull;

// Scratch gx = h_proj @ W_ih^T + b_ih, layout [t][j][s]
__device__ float g_gx[(size_t)T_DIM * G3 * S_DIM];

// ---- packed f32x2 helpers (GRU) ----
__device__ __forceinline__ ull dup2(float x) {
    ull r; asm("mov.b64 %0, {%1, %1};" : "=l"(r) : "f"(x)); return r;
}
__device__ __forceinline__ void fma2(ull& d, ull a, ull b) {
    asm("fma.rn.f32x2 %0, %1, %2, %0;" : "+l"(d) : "l"(a), "l"(b));
}
__device__ __forceinline__ float2 unpk(ull v) {
    float2 f; asm("mov.b64 {%0, %1}, %2;" : "=f"(f.x), "=f"(f.y) : "l"(v)); return f;
}

// ---- fp16 mma helper (phase 1): m16n8k16, f32 accumulate ----
__device__ __forceinline__ void mma_f16(float4& d,
    uint32_t a0, uint32_t a1, uint32_t a2, uint32_t a3,
    uint32_t b0, uint32_t b1)
{
    asm volatile(
      "mma.sync.aligned.m16n8k16.row.col.f32.f16.f16.f32 "
      "{%0,%1,%2,%3}, {%4,%5,%6,%7}, {%8,%9}, {%0,%1,%2,%3};"
      : "+f"(d.x), "+f"(d.y), "+f"(d.z), "+f"(d.w)
      : "r"(a0), "r"(a1), "r"(a2), "r"(a3), "r"(b0), "r"(b1));
}

__device__ __forceinline__ uint32_t h2u(__half2 h) {
    return *reinterpret_cast<uint32_t*>(&h);
}

// ---------------------------------------------------------------------------
// Phase 1: MLP + gx projection on fp16 tensor cores (m16n8k16, f32 acc).
// 4096 blocks x 256 thr; 128 rows/block; 87KB smem -> 2 blocks/SM.
// All operands staged as packed half2 in fragment layout:
//   B[nt][chunk][k2][n8] word = tig*8+gid per lane -> conflict-free.
//   A rows padded so word-stride ≡ 4 (mod 32) -> conflict-free.
// GEMM3 in 2 passes of 12 N-tiles (<=128 regs for 2 blocks/SM).
// ---------------------------------------------------------------------------
#define BS1H  0        // 2048 words (W1 half2)
#define BS2H  2048     // 1024 words (W2 half2)
#define BS3H  3072     // 6144 words (Wih half2)
#define B1F   9216     // 32 f32
#define B2F   9248     // 64 f32
#define BIHF  9312     // 192 f32
#define H1H   9504     // 8 warps * 16*20 = 2560 words (h1 half2)
#define XH    12064    // 128*68 = 8704 words (x half2; dead after GEMM1)
#define H2H   12064    // 8 warps * 16*36 = 4608 words (aliases XH)
#define CHKF  16672    // 8 warps * 32*20 = 5120 f32 (aliases XH tail)
#define SMW   21792    // words -> 87168 bytes

__global__ void __launch_bounds__(256, 2) mlp_gx_tensor(
    const float* __restrict__ x,
    const float* __restrict__ W1, const float* __restrict__ b1,
    const float* __restrict__ W2, const float* __restrict__ b2,
    const float* __restrict__ Wih, const float* __restrict__ bih)
{
    extern __shared__ uint32_t sm4[];
    float* smf = reinterpret_cast<float*>(sm4);

    const int tid  = threadIdx.x;
    const int w    = tid >> 5;
    const int lane = tid & 31;
    const int gid  = lane >> 2;
    const int tig  = lane & 3;

    // ---- stage weights as half2 fragment layout ----
    // W1 (128,32): word = nt*512 + chunk*64 + k2*8 + n8, halves (k, k+1)
    for (int i = tid; i < 2048; i += 256) {
        int nt = i >> 9, rem = i & 511;
        int chunk = rem >> 6, r2 = rem & 63;
        int k = chunk * 16 + (r2 >> 3) * 2, n = nt * 8 + (r2 & 7);
        sm4[BS1H + i] = h2u(__floats2half2_rn(W1[k * 32 + n], W1[(k + 1) * 32 + n]));
    }
    // W2 (32,64): word = nt*128 + chunk*64 + k2*8 + n8
    for (int i = tid; i < 1024; i += 256) {
        int nt = i >> 7, rem = i & 127;
        int chunk = rem >> 6, r2 = rem & 63;
        int k = chunk * 16 + (r2 >> 3) * 2, n = nt * 8 + (r2 & 7);
        sm4[BS2H + i] = h2u(__floats2half2_rn(W2[k * 64 + n], W2[(k + 1) * 64 + n]));
    }
    // Wih (192,64) as B(k=64, n=j=192): word = nt*256 + chunk*64 + k2*8 + n8
    for (int i = tid; i < 6144; i += 256) {
        int nt = i >> 8, rem = i & 255;
        int chunk = rem >> 6, r2 = rem & 63;
        int k = chunk * 16 + (r2 >> 3) * 2, j = nt * 8 + (r2 & 7);
        float2 wv = *reinterpret_cast<const float2*>(Wih + (size_t)j * 64 + k);
        sm4[BS3H + i] = h2u(__floats2half2_rn(wv.x, wv.y));
    }
    if (tid < 32)  smf[B1F + tid]  = b1[tid];
    if (tid < 64)  smf[B2F + tid]  = b2[tid];
    if (tid < 192) smf[BIHF + tid] = bih[tid];

    const int rowblock = blockIdx.x * 128;
    const int t  = rowblock >> 11;
    const int s0 = (rowblock & 2047) + w * 16;

    // ---- stage x tile as half2: 128 rows x 64 words (stride 68) ----
    {
        const float4* xg = reinterpret_cast<const float4*>(x) + (size_t)rowblock * 32;
        #pragma unroll
        for (int it = 0; it < 16; it++) {
            int fi = tid + it * 256;             // 4096 float4
            int r = fi >> 5, c4 = fi & 31;
            float4 v = __ldg(&xg[(size_t)r * 32 + c4]);
            sm4[XH + r * 68 + c4 * 2]     = h2u(__floats2half2_rn(v.x, v.y));
            sm4[XH + r * 68 + c4 * 2 + 1] = h2u(__floats2half2_rn(v.z, v.w));
        }
    }
    __syncthreads();

    const uint32_t* xh0 = sm4 + XH + (w * 16 + 0) * 68;   // rows gid
    const uint32_t* xh8 = sm4 + XH + (w * 16 + 8) * 68;   // rows gid+8
    uint32_t* h1h = sm4 + H1H + w * 320;                  // [16][20] half2

    // ========== GEMM1: x(16x128) @ W1(128x32), 8 k16-chunks ==========
    float4 acc1[4];
    #pragma unroll
    for (int nt = 0; nt < 4; nt++) {
        float bx = smf[B1F + nt * 8 + 2 * tig];
        float by = smf[B1F + nt * 8 + 2 * tig + 1];
        acc1[nt] = make_float4(bx, by, bx, by);
    }
    #pragma unroll
    for (int ch = 0; ch < 8; ch++) {
        uint32_t a0 = xh0[gid * 68 + ch * 8 + tig];
        uint32_t a1 = xh8[gid * 68 + ch * 8 + tig];
        uint32_t a2 = xh0[gid * 68 + ch * 8 + tig + 4];
        uint32_t a3 = xh8[gid * 68 + ch * 8 + tig + 4];
        #pragma unroll
        for (int nt = 0; nt < 4; nt++) {
            uint32_t b0 = sm4[BS1H + nt * 512 + ch * 64 + tig * 8 + gid];
            uint32_t b1v = sm4[BS1H + nt * 512 + ch * 64 + 32 + tig * 8 + gid];
            mma_f16(acc1[nt], a0, a1, a2, a3, b0, b1v);
        }
    }
    // lrelu + store h1 as half2: word = row*20 + (nt>>1)*8 + (nt&1)*4 + tig
    #pragma unroll
    for (int nt = 0; nt < 4; nt++) {
        int wd = (nt >> 1) * 8 + (nt & 1) * 4 + tig;
        float vx = acc1[nt].x, vy = acc1[nt].y, vz = acc1[nt].z, vw = acc1[nt].w;
        h1h[gid * 20 + wd] = h2u(__floats2half2_rn(fmaxf(vx, 0.01f * vx),
                                                   fmaxf(vy, 0.01f * vy)));
        h1h[(gid + 8) * 20 + wd] = h2u(__floats2half2_rn(fmaxf(vz, 0.01f * vz),
                                                         fmaxf(vw, 0.01f * vw)));
    }
    __syncthreads();   // all warps done with X region -> safe to alias (H2H/CHK)

    uint32_t* h2h = sm4 + H2H + w * 576;       // [16][36] half2
    float* chk = smf + CHKF + w * 640;         // [32][20] f32

    // ========== GEMM2: h1(16x32) @ W2(32x64), 2 k16-chunks ==========
    float4 acc2[8];
    #pragma unroll
    for (int nt = 0; nt < 8; nt++) {
        float bx = smf[B2F + nt * 8 + 2 * tig];
        float by = smf[B2F + nt * 8 + 2 * tig + 1];
        acc2[nt] = make_float4(bx, by, bx, by);
    }
    #pragma unroll
    for (int ch = 0; ch < 2; ch++) {
        uint32_t a0 = h1h[gid * 20 + ch * 8 + tig];
        uint32_t a1 = h1h[(gid + 8) * 20 + ch * 8 + tig];
        uint32_t a2 = h1h[gid * 20 + ch * 8 + tig + 4];
        uint32_t a3 = h1h[(gid + 8) * 20 + ch * 8 + tig + 4];
        #pragma unroll
        for (int nt = 0; nt < 8; nt++) {
            uint32_t b0 = sm4[BS2H + nt * 128 + ch * 64 + tig * 8 + gid];
            uint32_t b1v = sm4[BS2H + nt * 128 + ch * 64 + 32 + tig * 8 + gid];
            mma_f16(acc2[nt], a0, a1, a2, a3, b0, b1v);
        }
    }
    // lrelu + store h2 as half2: word = row*36 + (nt>>1)*8 + (nt&1)*4 + tig
    #pragma unroll
    for (int nt = 0; nt < 8; nt++) {
        int wd = (nt >> 1) * 8 + (nt & 1) * 4 + tig;
        float vx = acc2[nt].x, vy = acc2[nt].y, vz = acc2[nt].z, vw = acc2[nt].w;
        h2h[gid * 36 + wd] = h2u(__floats2half2_rn(fmaxf(vx, 0.01f * vx),
                                                   fmaxf(vy, 0.01f * vy)));
        h2h[(gid + 8) * 36 + wd] = h2u(__floats2half2_rn(fmaxf(vz, 0.01f * vz),
                                                         fmaxf(vw, 0.01f * vw)));
    }
    __syncwarp();

    // A-fragments for GEMM3 (4 chunks x 4 words = 16 regs, reused both passes)
    uint32_t areg3[16];
    #pragma unroll
    for (int ch = 0; ch < 4; ch++) {
        areg3[ch*4+0] = h2h[gid * 36 + ch * 8 + tig];
        areg3[ch*4+1] = h2h[(gid + 8) * 36 + ch * 8 + tig];
        areg3[ch*4+2] = h2h[gid * 36 + ch * 8 + tig + 4];
        areg3[ch*4+3] = h2h[(gid + 8) * 36 + ch * 8 + tig + 4];
    }

    // ====== GEMM3: h2(16x64) @ Wih^T(64x192), 2 passes x 12 N-tiles ======
    float* gx_t = g_gx + (size_t)t * G3 * S_DIM + s0;
    #pragma unroll 1
    for (int p = 0; p < 2; p++) {
        float4 acc3[12];
        #pragma unroll
        for (int q = 0; q < 12; q++) {
            int nt = p * 12 + q;
            float bx = smf[BIHF + nt * 8 + 2 * tig];
            float by = smf[BIHF + nt * 8 + 2 * tig + 1];
            acc3[q] = make_float4(bx, by, bx, by);
        }
        #pragma unroll
        for (int ch = 0; ch < 4; ch++) {
            #pragma unroll
            for (int q = 0; q < 12; q++) {
                int nt = p * 12 + q;
                uint32_t b0 = sm4[BS3H + nt * 256 + ch * 64 + tig * 8 + gid];
                uint32_t b1v = sm4[BS3H + nt * 256 + ch * 64 + 32 + tig * 8 + gid];
                mma_f16(acc3[q], areg3[ch*4+0], areg3[ch*4+1],
                                 areg3[ch*4+2], areg3[ch*4+3], b0, b1v);
            }
        }
        // transpose + store, 3 groups of 4 N-tiles (32 columns each)
        #pragma unroll
        for (int grp = 0; grp < 3; grp++) {
            #pragma unroll
            for (int q = 0; q < 4; q++) {
                float4 a = acc3[grp * 4 + q];
                int c = q * 8 + 2 * tig;
                chk[c * 20 + gid]           = a.x;
                chk[(c + 1) * 20 + gid]     = a.y;
                chk[c * 20 + gid + 8]       = a.z;
                chk[(c + 1) * 20 + gid + 8] = a.w;
            }
            __syncwarp();
            const int colbase = p * 96 + grp * 32;
            #pragma unroll
            for (int q8 = 0; q8 < 4; q8++) {
                int j = q8 * 8 + gid;
                float4 v = *reinterpret_cast<const float4*>(&chk[j * 20 + tig * 4]);
                *reinterpret_cast<float4*>(gx_t + (size_t)(colbase + j) * S_DIM + tig * 4) = v;
            }
            __syncwarp();
        }
    }
}

// ---------------------------------------------------------------------------
// Phase 2: GRU — EXACT R13 version (best measured, 577us).
// 256 blocks x 128 threads, 8 stocks/block. Thread = (j 0..63, kq 0..1):
// all 3 gates of column j; 12 independent fma2 chains per k-pair of LDS.
// ---------------------------------------------------------------------------
__global__ void __launch_bounds__(128, 2) gru_kernel(
    const float* __restrict__ Whh, const float* __restrict__ bhh,
    float* __restrict__ out)
{
    __shared__ float h_s[64 * 8];      // [k][s]
    __shared__ float gx_s[192 * 8];    // [j][s]

    const int tid = threadIdx.x;
    const int kq  = tid & 1;           // k half: [kq*32, kq*32+32)
    const int j   = tid >> 1;          // hidden column 0..63
    const int s0  = blockIdx.x * 8;

    float wR[32], wZ[32], wN[32];
    {
        const float4* pR = reinterpret_cast<const float4*>(Whh + (size_t)(      j) * L_DIM + kq * 32);
        const float4* pZ = reinterpret_cast<const float4*>(Whh + (size_t)( 64 + j) * L_DIM + kq * 32);
        const float4* pN = reinterpret_cast<const float4*>(Whh + (size_t)(128 + j) * L_DIM + kq * 32);
        #pragma unroll
        for (int q = 0; q < 8; q++) {
            float4 vR = __ldg(&pR[q]);
            float4 vZ = __ldg(&pZ[q]);
            float4 vN = __ldg(&pN[q]);
            wR[q*4+0]=vR.x; wR[q*4+1]=vR.y; wR[q*4+2]=vR.z; wR[q*4+3]=vR.w;
            wZ[q*4+0]=vZ.x; wZ[q*4+1]=vZ.y; wZ[q*4+2]=vZ.z; wZ[q*4+3]=vZ.w;
            wN[q*4+0]=vN.x; wN[q*4+1]=vN.y; wN[q*4+2]=vN.z; wN[q*4+3]=vN.w;
        }
    }
    const ull bR = (kq == 0) ? dup2(__ldg(&bhh[      j])) : 0ULL;
    const ull bZ = (kq == 0) ? dup2(__ldg(&bhh[ 64 + j])) : 0ULL;
    const ull bN = (kq == 0) ? dup2(__ldg(&bhh[128 + j])) : 0ULL;

    for (int i = tid; i < 64 * 8; i += 128) h_s[i] = 0.0f;
    __syncthreads();

    const float* hp = h_s + kq * 32 * 8;

    for (int t = 0; t < T_DIM; t++) {
        float gbuf[12];
        #pragma unroll
        for (int i = 0; i < 12; i++) {
            int idx = tid + 128 * i;
            int jj = idx >> 3, ss = idx & 7;
            gbuf[i] = __ldg(&g_gx[((size_t)t * G3 + jj) * S_DIM + s0 + ss]);
        }

        ull aR0 = bR, aR1 = bR, aR2 = bR, aR3 = bR;
        ull aZ0 = bZ, aZ1 = bZ, aZ2 = bZ, aZ3 = bZ;
        ull aN0 = bN, aN1 = bN, aN2 = bN, aN3 = bN;
        #pragma unroll
        for (int k = 0; k < 32; k++) {
            ulonglong2 hA = *reinterpret_cast<const ulonglong2*>(hp + k * 8);
            ulonglong2 hB = *reinterpret_cast<const ulonglong2*>(hp + k * 8 + 4);
            ull dR = dup2(wR[k]);
            fma2(aR0, hA.x, dR); fma2(aR1, hA.y, dR);
            fma2(aR2, hB.x, dR); fma2(aR3, hB.y, dR);
            ull dZ = dup2(wZ[k]);
            fma2(aZ0, hA.x, dZ); fma2(aZ1, hA.y, dZ);
            fma2(aZ2, hB.x, dZ); fma2(aZ3, hB.y, dZ);
            ull dN = dup2(wN[k]);
            fma2(aN0, hA.x, dN); fma2(aN1, hA.y, dN);
            fma2(aN2, hB.x, dN); fma2(aN3, hB.y, dN);
        }

        float ghR[4], ghZ[4], ghN[4];
        {
            float2 r0 = unpk(aR0), r1 = unpk(aR1), r2 = unpk(aR2), r3 = unpk(aR3);
            float2 z0 = unpk(aZ0), z1 = unpk(aZ1), z2 = unpk(aZ2), z3 = unpk(aZ3);
            float2 n0 = unpk(aN0), n1 = unpk(aN1), n2 = unpk(aN2), n3 = unpk(aN3);
            float gr[8] = {r0.x,r0.y,r1.x,r1.y,r2.x,r2.y,r3.x,r3.y};
            float gz[8] = {z0.x,z0.y,z1.x,z1.y,z2.x,z2.y,z3.x,z3.y};
            float gn[8] = {n0.x,n0.y,n1.x,n1.y,n2.x,n2.y,n3.x,n3.y};
            #pragma unroll
            for (int i = 0; i < 8; i++) {
                gr[i] += __shfl_xor_sync(0xFFFFFFFFu, gr[i], 1);
                gz[i] += __shfl_xor_sync(0xFFFFFFFFu, gz[i], 1);
                gn[i] += __shfl_xor_sync(0xFFFFFFFFu, gn[i], 1);
            }
            #pragma unroll
            for (int e = 0; e < 4; e++) {
                ghR[e] = kq ? gr[4 + e] : gr[e];
                ghZ[e] = kq ? gz[4 + e] : gz[e];
                ghN[e] = kq ? gn[4 + e] : gn[e];
            }
        }

        #pragma unroll
        for (int i = 0; i < 12; i++) {
            int idx = tid + 128 * i;
            int jj = idx >> 3, ss = idx & 7;
            gx_s[jj * 8 + ss] = gbuf[i];
        }
        __syncthreads();

        {
            const int sb = kq * 4;
            float4 gxr = *reinterpret_cast<const float4*>(&gx_s[(      j) * 8 + sb]);
            float4 gxz = *reinterpret_cast<const float4*>(&gx_s[( 64 + j) * 8 + sb]);
            float4 gxn = *reinterpret_cast<const float4*>(&gx_s[(128 + j) * 8 + sb]);
            float4 hold = *reinterpret_cast<const float4*>(&h_s[j * 8 + sb]);
            float gxra[4] = {gxr.x, gxr.y, gxr.z, gxr.w};
            float gxza[4] = {gxz.x, gxz.y, gxz.z, gxz.w};
            float gxna[4] = {gxn.x, gxn.y, gxn.z, gxn.w};
            float hoa[4]  = {hold.x, hold.y, hold.z, hold.w};

            float hn[4];
            #pragma unroll
            for (int e = 0; e < 4; e++) {
                float rr = 1.0f / (1.0f + __expf(-(gxra[e] + ghR[e])));
                float zz = 1.0f / (1.0f + __expf(-(gxza[e] + ghZ[e])));
                float narg = gxna[e] + rr * ghN[e];
                float ex = __expf(-2.0f * fabsf(narg));
                float nn = (1.0f - ex) / (1.0f + ex);
                nn = copysignf(nn, narg);
                hn[e] = (1.0f - zz) * nn + zz * hoa[e];
            }
            *reinterpret_cast<float4*>(&h_s[j * 8 + sb]) =
                make_float4(hn[0], hn[1], hn[2], hn[3]);
        }
        __syncthreads();
    }

    for (int idx = tid; idx < 512; idx += 128) {
        int jj = idx & 63, ss = idx >> 6;
        out[(size_t)(s0 + ss) * L_DIM + jj] = h_s[jj * 8 + ss];
    }
}

// ---------------------------------------------------------------------------
extern "C" void kernel_launch(void* const* d_in, const int* in_sizes, int n_in,
                              void* d_out, int out_size)
{
    const float* x   = (const float*)d_in[0];
    const float* W1  = (const float*)d_in[1];
    const float* b1  = (const float*)d_in[2];
    const float* W2  = (const float*)d_in[3];
    const float* b2  = (const float*)d_in[4];
    const float* Wih = (const float*)d_in[5];
    const float* Whh = (const float*)d_in[6];
    const float* bih = (const float*)d_in[7];
    const float* bhh = (const float*)d_in[8];
    float* out = (float*)d_out;

    static bool attrs_set = false;
    if (!attrs_set) {
        cudaFuncSetAttribute(mlp_gx_tensor,
                             cudaFuncAttributeMaxDynamicSharedMemorySize, SMW * 4);
        attrs_set = true;
    }

    // Phase 1: 4096 blocks x 256 threads; 128 rows/block; fp16 mma, 2 blk/SM
    mlp_gx_tensor<<<4096, 256, SMW * 4>>>(x, W1, b1, W2, b2, Wih, bih);
    // Phase 2: GRU, 256 blocks x 128 threads, 8 stocks/block
    gru_kernel<<<256, 128>>>(Whh, bhh, out);
}

// round 17
// speedup vs baseline: 1.4513x; 1.1343x over previous
#include <cuda_runtime.h>
#include <cuda_fp16.h>
#include <math.h>
#include <stdint.h>

#define T_DIM 256
#define S_DIM 2048
#define C_DIM 128
#define G3    192
#define L_DIM 64

typedef unsigned long long ull;

// Scratch gx = h_proj @ W_ih^T + b_ih, layout [t][j][s]
__device__ float g_gx[(size_t)T_DIM * G3 * S_DIM];

// ---- fp16 mma helper: m16n8k16, f32 accumulate ----
__device__ __forceinline__ void mma_f16(float4& d,
    uint32_t a0, uint32_t a1, uint32_t a2, uint32_t a3,
    uint32_t b0, uint32_t b1)
{
    asm volatile(
      "mma.sync.aligned.m16n8k16.row.col.f32.f16.f16.f32 "
      "{%0,%1,%2,%3}, {%4,%5,%6,%7}, {%8,%9}, {%0,%1,%2,%3};"
      : "+f"(d.x), "+f"(d.y), "+f"(d.z), "+f"(d.w)
      : "r"(a0), "r"(a1), "r"(a2), "r"(a3), "r"(b0), "r"(b1));
}

__device__ __forceinline__ uint32_t h2u(__half2 h) {
    return *reinterpret_cast<uint32_t*>(&h);
}

// ---------------------------------------------------------------------------
// Phase 1: MLP + gx projection on fp16 tensor cores — EXACT R16 version
// (~233us measured). 4096 blocks x 256 thr; 2 blocks/SM.
// ---------------------------------------------------------------------------
#define BS1H  0
#define BS2H  2048
#define BS3H  3072
#define B1F   9216
#define B2F   9248
#define BIHF  9312
#define H1H   9504
#define XH    12064
#define H2H   12064
#define CHKF  16672
#define SMW   21792

__global__ void __launch_bounds__(256, 2) mlp_gx_tensor(
    const float* __restrict__ x,
    const float* __restrict__ W1, const float* __restrict__ b1,
    const float* __restrict__ W2, const float* __restrict__ b2,
    const float* __restrict__ Wih, const float* __restrict__ bih)
{
    extern __shared__ uint32_t sm4[];
    float* smf = reinterpret_cast<float*>(sm4);

    const int tid  = threadIdx.x;
    const int w    = tid >> 5;
    const int lane = tid & 31;
    const int gid  = lane >> 2;
    const int tig  = lane & 3;

    for (int i = tid; i < 2048; i += 256) {
        int nt = i >> 9, rem = i & 511;
        int chunk = rem >> 6, r2 = rem & 63;
        int k = chunk * 16 + (r2 >> 3) * 2, n = nt * 8 + (r2 & 7);
        sm4[BS1H + i] = h2u(__floats2half2_rn(W1[k * 32 + n], W1[(k + 1) * 32 + n]));
    }
    for (int i = tid; i < 1024; i += 256) {
        int nt = i >> 7, rem = i & 127;
        int chunk = rem >> 6, r2 = rem & 63;
        int k = chunk * 16 + (r2 >> 3) * 2, n = nt * 8 + (r2 & 7);
        sm4[BS2H + i] = h2u(__floats2half2_rn(W2[k * 64 + n], W2[(k + 1) * 64 + n]));
    }
    for (int i = tid; i < 6144; i += 256) {
        int nt = i >> 8, rem = i & 255;
        int chunk = rem >> 6, r2 = rem & 63;
        int k = chunk * 16 + (r2 >> 3) * 2, j = nt * 8 + (r2 & 7);
        float2 wv = *reinterpret_cast<const float2*>(Wih + (size_t)j * 64 + k);
        sm4[BS3H + i] = h2u(__floats2half2_rn(wv.x, wv.y));
    }
    if (tid < 32)  smf[B1F + tid]  = b1[tid];
    if (tid < 64)  smf[B2F + tid]  = b2[tid];
    if (tid < 192) smf[BIHF + tid] = bih[tid];

    const int rowblock = blockIdx.x * 128;
    const int t  = rowblock >> 11;
    const int s0 = (rowblock & 2047) + w * 16;

    {
        const float4* xg = reinterpret_cast<const float4*>(x) + (size_t)rowblock * 32;
        #pragma unroll
        for (int it = 0; it < 16; it++) {
            int fi = tid + it * 256;
            int r = fi >> 5, c4 = fi & 31;
            float4 v = __ldg(&xg[(size_t)r * 32 + c4]);
            sm4[XH + r * 68 + c4 * 2]     = h2u(__floats2half2_rn(v.x, v.y));
            sm4[XH + r * 68 + c4 * 2 + 1] = h2u(__floats2half2_rn(v.z, v.w));
        }
    }
    __syncthreads();

    const uint32_t* xh0 = sm4 + XH + (w * 16 + 0) * 68;
    const uint32_t* xh8 = sm4 + XH + (w * 16 + 8) * 68;
    uint32_t* h1h = sm4 + H1H + w * 320;

    float4 acc1[4];
    #pragma unroll
    for (int nt = 0; nt < 4; nt++) {
        float bx = smf[B1F + nt * 8 + 2 * tig];
        float by = smf[B1F + nt * 8 + 2 * tig + 1];
        acc1[nt] = make_float4(bx, by, bx, by);
    }
    #pragma unroll
    for (int ch = 0; ch < 8; ch++) {
        uint32_t a0 = xh0[gid * 68 + ch * 8 + tig];
        uint32_t a1 = xh8[gid * 68 + ch * 8 + tig];
        uint32_t a2 = xh0[gid * 68 + ch * 8 + tig + 4];
        uint32_t a3 = xh8[gid * 68 + ch * 8 + tig + 4];
        #pragma unroll
        for (int nt = 0; nt < 4; nt++) {
            uint32_t b0 = sm4[BS1H + nt * 512 + ch * 64 + tig * 8 + gid];
            uint32_t b1v = sm4[BS1H + nt * 512 + ch * 64 + 32 + tig * 8 + gid];
            mma_f16(acc1[nt], a0, a1, a2, a3, b0, b1v);
        }
    }
    #pragma unroll
    for (int nt = 0; nt < 4; nt++) {
        int wd = (nt >> 1) * 8 + (nt & 1) * 4 + tig;
        float vx = acc1[nt].x, vy = acc1[nt].y, vz = acc1[nt].z, vw = acc1[nt].w;
        h1h[gid * 20 + wd] = h2u(__floats2half2_rn(fmaxf(vx, 0.01f * vx),
                                                   fmaxf(vy, 0.01f * vy)));
        h1h[(gid + 8) * 20 + wd] = h2u(__floats2half2_rn(fmaxf(vz, 0.01f * vz),
                                                         fmaxf(vw, 0.01f * vw)));
    }
    __syncthreads();

    uint32_t* h2h = sm4 + H2H + w * 576;
    float* chk = smf + CHKF + w * 640;

    float4 acc2[8];
    #pragma unroll
    for (int nt = 0; nt < 8; nt++) {
        float bx = smf[B2F + nt * 8 + 2 * tig];
        float by = smf[B2F + nt * 8 + 2 * tig + 1];
        acc2[nt] = make_float4(bx, by, bx, by);
    }
    #pragma unroll
    for (int ch = 0; ch < 2; ch++) {
        uint32_t a0 = h1h[gid * 20 + ch * 8 + tig];
        uint32_t a1 = h1h[(gid + 8) * 20 + ch * 8 + tig];
        uint32_t a2 = h1h[gid * 20 + ch * 8 + tig + 4];
        uint32_t a3 = h1h[(gid + 8) * 20 + ch * 8 + tig + 4];
        #pragma unroll
        for (int nt = 0; nt < 8; nt++) {
            uint32_t b0 = sm4[BS2H + nt * 128 + ch * 64 + tig * 8 + gid];
            uint32_t b1v = sm4[BS2H + nt * 128 + ch * 64 + 32 + tig * 8 + gid];
            mma_f16(acc2[nt], a0, a1, a2, a3, b0, b1v);
        }
    }
    #pragma unroll
    for (int nt = 0; nt < 8; nt++) {
        int wd = (nt >> 1) * 8 + (nt & 1) * 4 + tig;
        float vx = acc2[nt].x, vy = acc2[nt].y, vz = acc2[nt].z, vw = acc2[nt].w;
        h2h[gid * 36 + wd] = h2u(__floats2half2_rn(fmaxf(vx, 0.01f * vx),
                                                   fmaxf(vy, 0.01f * vy)));
        h2h[(gid + 8) * 36 + wd] = h2u(__floats2half2_rn(fmaxf(vz, 0.01f * vz),
                                                         fmaxf(vw, 0.01f * vw)));
    }
    __syncwarp();

    uint32_t areg3[16];
    #pragma unroll
    for (int ch = 0; ch < 4; ch++) {
        areg3[ch*4+0] = h2h[gid * 36 + ch * 8 + tig];
        areg3[ch*4+1] = h2h[(gid + 8) * 36 + ch * 8 + tig];
        areg3[ch*4+2] = h2h[gid * 36 + ch * 8 + tig + 4];
        areg3[ch*4+3] = h2h[(gid + 8) * 36 + ch * 8 + tig + 4];
    }

    float* gx_t = g_gx + (size_t)t * G3 * S_DIM + s0;
    #pragma unroll 1
    for (int p = 0; p < 2; p++) {
        float4 acc3[12];
        #pragma unroll
        for (int q = 0; q < 12; q++) {
            int nt = p * 12 + q;
            float bx = smf[BIHF + nt * 8 + 2 * tig];
            float by = smf[BIHF + nt * 8 + 2 * tig + 1];
            acc3[q] = make_float4(bx, by, bx, by);
        }
        #pragma unroll
        for (int ch = 0; ch < 4; ch++) {
            #pragma unroll
            for (int q = 0; q < 12; q++) {
                int nt = p * 12 + q;
                uint32_t b0 = sm4[BS3H + nt * 256 + ch * 64 + tig * 8 + gid];
                uint32_t b1v = sm4[BS3H + nt * 256 + ch * 64 + 32 + tig * 8 + gid];
                mma_f16(acc3[q], areg3[ch*4+0], areg3[ch*4+1],
                                 areg3[ch*4+2], areg3[ch*4+3], b0, b1v);
            }
        }
        #pragma unroll
        for (int grp = 0; grp < 3; grp++) {
            #pragma unroll
            for (int q = 0; q < 4; q++) {
                float4 a = acc3[grp * 4 + q];
                int c = q * 8 + 2 * tig;
                chk[c * 20 + gid]           = a.x;
                chk[(c + 1) * 20 + gid]     = a.y;
                chk[c * 20 + gid + 8]       = a.z;
                chk[(c + 1) * 20 + gid + 8] = a.w;
            }
            __syncwarp();
            const int colbase = p * 96 + grp * 32;
            #pragma unroll
            for (int q8 = 0; q8 < 4; q8++) {
                int j = q8 * 8 + gid;
                float4 v = *reinterpret_cast<const float4*>(&chk[j * 20 + tig * 4]);
                *reinterpret_cast<float4*>(gx_t + (size_t)(colbase + j) * S_DIM + tig * 4) = v;
            }
            __syncwarp();
        }
    }
}

// ---------------------------------------------------------------------------
// Phase 2: GRU on fp16 tensor cores with split-precision operands.
// 128 blocks x 256 threads (8 warps), 16 stocks/block, 1 block/SM.
// gh(16x192) = h(16x64) @ Whh^T via m16n8k16:
//   gh ≈ Whi·h_hi + Whi·h_lo + Wlo·h_hi   (error ~1e-6, fp32-grade)
// Whh hi/lo B-fragments hoisted into 48 registers (constant over t).
// h kept as fp32 (gates) + fp16 hi/lo (A operands, stride-36 frag layout).
// Warp w computes gj columns w*24..w*24+23 (3 N-tiles). 2 barriers/step.
// ---------------------------------------------------------------------------
__global__ void __launch_bounds__(256, 1) gru_kernel(
    const float* __restrict__ Whh, const float* __restrict__ bhh,
    float* __restrict__ out)
{
    __shared__ float    gh_s[16 * 196];   // [s][gj]
    __shared__ float    gx_s[16 * 196];   // [s][gj]
    __shared__ float    h_s [16 * 68];    // [s][j] fp32
    __shared__ uint32_t hhi_w[16 * 36];   // h_hi half2 words, A-frag layout
    __shared__ uint32_t hlo_w[16 * 36];   // h_lo

    const int tid  = threadIdx.x;
    const int w    = tid >> 5;
    const int lane = tid & 31;
    const int gid  = lane >> 2;
    const int tig  = lane & 3;
    const int s0   = blockIdx.x * 16;

    // ---- hoist Whh hi/lo B-fragments into registers (once) ----
    uint32_t bHi[24], bLo[24];
    #pragma unroll
    for (int ln = 0; ln < 3; ln++) {
        int n = (w * 3 + ln) * 8 + gid;       // gj column
        #pragma unroll
        for (int ch = 0; ch < 4; ch++) {
            #pragma unroll
            for (int hv = 0; hv < 2; hv++) {
                int k = ch * 16 + (tig + hv * 4) * 2;
                float2 wv = *reinterpret_cast<const float2*>(Whh + (size_t)n * 64 + k);
                __half hx = __float2half_rn(wv.x);
                __half hy = __float2half_rn(wv.y);
                __half lx = __float2half_rn(wv.x - __half2float(hx));
                __half ly = __float2half_rn(wv.y - __half2float(hy));
                bHi[(ln * 4 + ch) * 2 + hv] = h2u(__halves2half2(hx, hy));
                bLo[(ln * 4 + ch) * 2 + hv] = h2u(__halves2half2(lx, ly));
            }
        }
    }

    // gate-phase constants: thread = (j = tid&63, stock quad gsq = tid>>6)
    const int gj  = tid & 63;
    const int gsq = tid >> 6;
    const float bRv = __ldg(&bhh[gj]);
    const float bZv = __ldg(&bhh[64 + gj]);
    const float bNv = __ldg(&bhh[128 + gj]);

    for (int i = tid; i < 16 * 68; i += 256) h_s[i] = 0.0f;
    for (int i = tid; i < 16 * 36; i += 256) { hhi_w[i] = 0u; hlo_w[i] = 0u; }
    __syncthreads();

    __half* hhi_h = reinterpret_cast<__half*>(hhi_w);
    __half* hlo_h = reinterpret_cast<__half*>(hlo_w);

    for (int t = 0; t < T_DIM; t++) {
        // Prefetch gx tile (192*16 = 3072 floats, 12/thread)
        float gbuf[12];
        #pragma unroll
        for (int i = 0; i < 12; i++) {
            int idx = tid + 256 * i;
            int jj = idx >> 4, ss = idx & 15;
            gbuf[i] = __ldg(&g_gx[((size_t)t * G3 + jj) * S_DIM + s0 + ss]);
        }

        // A fragments: h_hi / h_lo (conflict-free: 4*gid + tig banks)
        uint32_t ahi[16], alo[16];
        #pragma unroll
        for (int ch = 0; ch < 4; ch++) {
            ahi[ch*4+0] = hhi_w[gid * 36 + ch * 8 + tig];
            ahi[ch*4+1] = hhi_w[(gid + 8) * 36 + ch * 8 + tig];
            ahi[ch*4+2] = hhi_w[gid * 36 + ch * 8 + tig + 4];
            ahi[ch*4+3] = hhi_w[(gid + 8) * 36 + ch * 8 + tig + 4];
            alo[ch*4+0] = hlo_w[gid * 36 + ch * 8 + tig];
            alo[ch*4+1] = hlo_w[(gid + 8) * 36 + ch * 8 + tig];
            alo[ch*4+2] = hlo_w[gid * 36 + ch * 8 + tig + 4];
            alo[ch*4+3] = hlo_w[(gid + 8) * 36 + ch * 8 + tig + 4];
        }

        // 36 mma: 3 N-tiles x 4 k-chunks x 3 split terms
        float4 acc[3];
        #pragma unroll
        for (int ln = 0; ln < 3; ln++) acc[ln] = make_float4(0.f, 0.f, 0.f, 0.f);
        #pragma unroll
        for (int ch = 0; ch < 4; ch++) {
            #pragma unroll
            for (int ln = 0; ln < 3; ln++) {
                uint32_t b0h = bHi[(ln*4+ch)*2], b1h = bHi[(ln*4+ch)*2+1];
                uint32_t b0l = bLo[(ln*4+ch)*2], b1l = bLo[(ln*4+ch)*2+1];
                mma_f16(acc[ln], ahi[ch*4+0], ahi[ch*4+1], ahi[ch*4+2], ahi[ch*4+3], b0h, b1h);
                mma_f16(acc[ln], alo[ch*4+0], alo[ch*4+1], alo[ch*4+2], alo[ch*4+3], b0h, b1h);
                mma_f16(acc[ln], ahi[ch*4+0], ahi[ch*4+1], ahi[ch*4+2], ahi[ch*4+3], b0l, b1l);
            }
        }

        // Store gh to smem [s][gj]
        #pragma unroll
        for (int ln = 0; ln < 3; ln++) {
            int cb = (w * 3 + ln) * 8 + 2 * tig;
            *reinterpret_cast<float2*>(&gh_s[gid * 196 + cb]) = make_float2(acc[ln].x, acc[ln].y);
            *reinterpret_cast<float2*>(&gh_s[(gid + 8) * 196 + cb]) = make_float2(acc[ln].z, acc[ln].w);
        }
        // Stage gx [s][gj]
        #pragma unroll
        for (int i = 0; i < 12; i++) {
            int idx = tid + 256 * i;
            int jj = idx >> 4, ss = idx & 15;
            gx_s[ss * 196 + jj] = gbuf[i];
        }
        __syncthreads();   // gh + gx visible; mma reads of h_hi/h_lo done

        // Gate math: thread (gj, gsq) handles stocks gsq*4..gsq*4+3
        #pragma unroll
        for (int si = 0; si < 4; si++) {
            int s = gsq * 4 + si;
            float ghr = gh_s[s * 196 + gj];
            float ghz = gh_s[s * 196 + 64 + gj];
            float ghn = gh_s[s * 196 + 128 + gj];
            float gxr = gx_s[s * 196 + gj];
            float gxz = gx_s[s * 196 + 64 + gj];
            float gxn = gx_s[s * 196 + 128 + gj];
            float ho  = h_s[s * 68 + gj];

            float rr = 1.0f / (1.0f + __expf(-(gxr + ghr + bRv)));
            float zz = 1.0f / (1.0f + __expf(-(gxz + ghz + bZv)));
            float narg = gxn + rr * (ghn + bNv);
            float ex = __expf(-2.0f * fabsf(narg));
            float nn = (1.0f - ex) / (1.0f + ex);
            nn = copysignf(nn, narg);
            float hn = (1.0f - zz) * nn + zz * ho;

            h_s[s * 68 + gj] = hn;
            __half hi = __float2half_rn(hn);
            hhi_h[s * 72 + gj] = hi;
            hlo_h[s * 72 + gj] = __float2half_rn(hn - __half2float(hi));
        }
        __syncthreads();   // new h (fp32 + hi/lo) visible before next step
    }

    // Final hidden state: out[(s0+s)*64 + j]
    for (int idx = tid; idx < 1024; idx += 256) {
        int jj = idx & 63, ss = idx >> 6;
        out[(size_t)(s0 + ss) * L_DIM + jj] = h_s[ss * 68 + jj];
    }
}

// ---------------------------------------------------------------------------
extern "C" void kernel_launch(void* const* d_in, const int* in_sizes, int n_in,
                              void* d_out, int out_size)
{
    const float* x   = (const float*)d_in[0];
    const float* W1  = (const float*)d_in[1];
    const float* b1  = (const float*)d_in[2];
    const float* W2  = (const float*)d_in[3];
    const float* b2  = (const float*)d_in[4];
    const float* Wih = (const float*)d_in[5];
    const float* Whh = (const float*)d_in[6];
    const float* bih = (const float*)d_in[7];
    const float* bhh = (const float*)d_in[8];
    float* out = (float*)d_out;

    static bool attrs_set = false;
    if (!attrs_set) {
        cudaFuncSetAttribute(mlp_gx_tensor,
                             cudaFuncAttributeMaxDynamicSharedMemorySize, SMW * 4);
        attrs_set = true;
    }

    // Phase 1: fp16 tensor cores, 4096 blocks x 256 threads (~233us)
    mlp_gx_tensor<<<4096, 256, SMW * 4>>>(x, W1, b1, W2, b2, Wih, bih);
    // Phase 2: GRU on fp16 tensor cores, 128 blocks x 256 threads, 16 stocks
    gru_kernel<<<128, 256>>>(Whh, bhh, out);
}